// round 14
// baseline (speedup 1.0000x reference)
#include <cuda_runtime.h>

// Shapes (fixed by the problem)
#define BB 8      // batch
#define NN 16     // support classes
#define DD 512    // input channels
#define UU 784    // H*W = 28*28 (spatial, both u and v)
#define KK 128    // projected dim DK

// -------------------- scratch (device globals; no allocs allowed) ----------
__device__ float g_qk [BB*KK*UU];   // [b][k][u]  Wk @ query
__device__ float g_qv [BB*KK*UU];   // [b][k][u]  Wv @ query   (= "b" matrix, k-major)
__device__ float g_sk [NN*KK*UU];   // [n][k][v]  Wk @ support
__device__ float g_sv [NN*KK*UU];   // [n][k][v]  Wv @ support
__device__ float g_skt[UU*NN*KK];   // [v][n][k]  transposed support keys
__device__ float g_svt[UU*NN*KK];   // [v][n][k]  transposed support values
__device__ float g_A  [BB*NN*UU];   // [b][n][v]  sum_u softmax_n(scores)
__device__ float g_al [BB*UU*KK];   // [b][v][k]  query_aligned (a matrix)
__device__ float g_a2 [BB*UU];      // ||a||^2 per (b,v)
__device__ float g_b2 [BB*UU];      // ||b||^2 per (b,u)
__device__ float g_part[BB*169];    // per-tile partial sums of clamped d2

// ============================================================================
// 1) Projections: out[g][k][u] = sum_d W[k][d] * x[g][d][u]
//    48 jobs: (8 b × {Wk,Wv}) on query, (16 n × {Wk,Wv}) on support.
//    Tile: BM=128 (all k), BN=64 (u), BK=16 (d). 256 thr, TM=8, TN=4.
// ============================================================================
__global__ __launch_bounds__(256) void proj_kernel(
    const float* __restrict__ query, const float* __restrict__ support,
    const float* __restrict__ Wk,    const float* __restrict__ Wv)
{
    int job = blockIdx.z;
    const float* x; float* out; const float* W;
    if (job < 16) {
        int g = job >> 1;
        x   = query + g * (DD*UU);
        W   = (job & 1) ? Wv : Wk;
        out = ((job & 1) ? g_qv : g_qk) + g * (KK*UU);
    } else {
        int idx = job - 16, g = idx >> 1;
        x   = support + g * (DD*UU);
        W   = (idx & 1) ? Wv : Wk;
        out = ((idx & 1) ? g_sv : g_sk) + g * (KK*UU);
    }
    const int u0  = blockIdx.x * 64;
    const int tid = threadIdx.x;
    const int ty  = tid >> 4;      // 0..15 -> k rows ty*8..+7
    const int tx  = tid & 15;      // 0..15 -> u cols tx*4..+3

    __shared__ float Ws[16][128];  // [d][k]  (transposed for conflict-free reads)
    __shared__ float Xs[16][64];   // [d][u]

    float acc[8][4];
    #pragma unroll
    for (int i = 0; i < 8; i++)
        #pragma unroll
        for (int j = 0; j < 4; j++) acc[i][j] = 0.f;

    for (int d0 = 0; d0 < DD; d0 += 16) {
        // W tile: 128k x 16d -> Ws[d][k]
        #pragma unroll
        for (int t = 0; t < 2; t++) {
            int t4 = tid * 2 + t;            // 0..511
            int k  = t4 >> 2;                // 0..127
            int c4 = t4 & 3;                 // 0..3
            float4 w = *reinterpret_cast<const float4*>(W + k * DD + d0 + c4 * 4);
            Ws[c4*4+0][k] = w.x;  Ws[c4*4+1][k] = w.y;
            Ws[c4*4+2][k] = w.z;  Ws[c4*4+3][k] = w.w;
        }
        // X tile: 16d x 64u
        {
            int row = tid >> 4;              // d
            int c4  = tid & 15;              // u/4
            int u   = u0 + c4 * 4;
            float4 xv = make_float4(0.f, 0.f, 0.f, 0.f);
            if (u < UU)
                xv = *reinterpret_cast<const float4*>(x + (d0 + row) * UU + u);
            *reinterpret_cast<float4*>(&Xs[row][c4 * 4]) = xv;
        }
        __syncthreads();
        #pragma unroll
        for (int dd = 0; dd < 16; dd++) {
            float4 wa = *reinterpret_cast<const float4*>(&Ws[dd][ty * 8]);
            float4 wb = *reinterpret_cast<const float4*>(&Ws[dd][ty * 8 + 4]);
            float4 xv = *reinterpret_cast<const float4*>(&Xs[dd][tx * 4]);
            float wr[8] = {wa.x, wa.y, wa.z, wa.w, wb.x, wb.y, wb.z, wb.w};
            float xr[4] = {xv.x, xv.y, xv.z, xv.w};
            #pragma unroll
            for (int i = 0; i < 8; i++)
                #pragma unroll
                for (int j = 0; j < 4; j++)
                    acc[i][j] += wr[i] * xr[j];
        }
        __syncthreads();
    }
    int u = u0 + tx * 4;
    if (u < UU) {
        #pragma unroll
        for (int i = 0; i < 8; i++) {
            int k = ty * 8 + i;
            float4 o = make_float4(acc[i][0], acc[i][1], acc[i][2], acc[i][3]);
            *reinterpret_cast<float4*>(out + k * UU + u) = o;
        }
    }
}

// ============================================================================
// 2) Transpose g_sk/g_sv [n][k][v] -> [v][n][k] for coalesced per-v access.
//    grid (25, 4, 32): x = v tile, y = k tile, z = n*2 + which
// ============================================================================
__global__ void transpose_kernel()
{
    const int which = blockIdx.z & 1;
    const int n     = blockIdx.z >> 1;
    const float* in = (which ? g_sv : g_sk) + n * (KK*UU);
    float* out      = (which ? g_svt : g_skt);
    __shared__ float s[32][33];
    const int v0 = blockIdx.x * 32, k0 = blockIdx.y * 32;
    const int tx = threadIdx.x, ty = threadIdx.y;   // 32 x 8
    #pragma unroll
    for (int j = 0; j < 4; j++) {
        int k = k0 + ty + j * 8, v = v0 + tx;
        s[ty + j * 8][tx] = (v < UU) ? in[k * UU + v] : 0.f;
    }
    __syncthreads();
    #pragma unroll
    for (int j = 0; j < 4; j++) {
        int v = v0 + ty + j * 8, k = k0 + tx;
        if (v < UU) out[v * (NN*KK) + n * KK + k] = s[tx][ty + j * 8];
    }
}

// ============================================================================
// 3) Attention: block = (v, b). Computes A[b][n][v] = sum_u softmax_n(scores).
//    Thread t<196 owns 4 consecutive u; keeps all 16 n in registers so the
//    softmax over n is thread-local (no cross-thread traffic). FFMA-bound.
// ============================================================================
__global__ __launch_bounds__(224, 2) void attn_kernel()
{
    const int v = blockIdx.x, b = blockIdx.y;
    const int tid = threadIdx.x;
    __shared__ float s_sk[NN * KK];     // [n][k] for this v
    __shared__ float s_red[7][16];

    for (int i = tid; i < NN * KK; i += 224)
        s_sk[i] = g_skt[v * (NN*KK) + i];
    __syncthreads();

    float partA[16];
    #pragma unroll
    for (int n = 0; n < 16; n++) partA[n] = 0.f;

    if (tid < 196) {
        const int u0 = tid * 4;         // 196*4 = 784 exactly
        float acc[64];                  // [n][uu]
        #pragma unroll
        for (int i = 0; i < 64; i++) acc[i] = 0.f;
        const float* qb = g_qk + b * (KK*UU) + u0;
        #pragma unroll 4
        for (int k = 0; k < KK; k++) {
            float4 q4 = *reinterpret_cast<const float4*>(qb + k * UU);
            #pragma unroll
            for (int n = 0; n < 16; n++) {
                float s = s_sk[n * KK + k];   // uniform -> broadcast LDS
                acc[n*4+0] += s * q4.x;
                acc[n*4+1] += s * q4.y;
                acc[n*4+2] += s * q4.z;
                acc[n*4+3] += s * q4.w;
            }
        }
        const float scale = 0.0883883476483184f;   // 1/sqrt(128)
        #pragma unroll
        for (int uu = 0; uu < 4; uu++) {
            float m = acc[uu];
            #pragma unroll
            for (int n = 1; n < 16; n++) m = fmaxf(m, acc[n*4+uu]);
            float e[16], sum = 0.f;
            #pragma unroll
            for (int n = 0; n < 16; n++) {
                e[n] = __expf((acc[n*4+uu] - m) * scale);
                sum += e[n];
            }
            float inv = 1.f / sum;
            #pragma unroll
            for (int n = 0; n < 16; n++) partA[n] += e[n] * inv;
        }
    }
    const int lane = tid & 31, warp = tid >> 5;
    #pragma unroll
    for (int n = 0; n < 16; n++) {
        float t = partA[n];
        #pragma unroll
        for (int off = 16; off; off >>= 1)
            t += __shfl_down_sync(0xffffffffu, t, off);
        if (lane == 0) s_red[warp][n] = t;
    }
    __syncthreads();
    if (tid < 16) {
        float s = 0.f;
        #pragma unroll
        for (int w = 0; w < 7; w++) s += s_red[w][tid];
        g_A[(b * 16 + tid) * UU + v] = s;
    }
}

// ============================================================================
// 4) Align: a[b][v][k] = sum_n A[b][n][v] * sv[n][k][v]; also a2[b][v].
// ============================================================================
__global__ __launch_bounds__(128) void align_kernel()
{
    const int v = blockIdx.x, b = blockIdx.y, k = threadIdx.x;
    __shared__ float a_sm[16];
    __shared__ float red[4];
    if (k < 16) a_sm[k] = g_A[(b * 16 + k) * UU + v];
    __syncthreads();
    const float* sv = g_svt + v * (NN*KK) + k;
    float acc = 0.f;
    #pragma unroll
    for (int n = 0; n < 16; n++) acc += a_sm[n] * sv[n * KK];
    g_al[(b * UU + v) * KK + k] = acc;
    float sq = acc * acc;
    #pragma unroll
    for (int off = 16; off; off >>= 1)
        sq += __shfl_down_sync(0xffffffffu, sq, off);
    if ((k & 31) == 0) red[k >> 5] = sq;
    __syncthreads();
    if (k == 0) g_a2[b * UU + v] = red[0] + red[1] + red[2] + red[3];
}

// ============================================================================
// 5) b2[b][u] = sum_k qv[b][k][u]^2
// ============================================================================
__global__ void b2_kernel()
{
    const int b = blockIdx.y;
    const int u = blockIdx.x * 256 + threadIdx.x;
    if (u >= UU) return;
    const float* q = g_qv + b * (KK*UU) + u;
    float s = 0.f;
    #pragma unroll 8
    for (int k = 0; k < KK; k++) { float x = q[k * UU]; s += x * x; }
    g_b2[b * UU + u] = s;
}

// ============================================================================
// 6) Distance: per b, sum_{p,r} max(a2[p]+b2[r]-2*dot(a[p,:],bmat[r,:]), 0).
//    a is [v][k] row-major, qv is already [k][u] -> classic C = A*B tiling.
//    64x64 tile, 256 thr, 4x4 per thread; tile partial -> g_part (deterministic).
// ============================================================================
__global__ __launch_bounds__(256) void dist_kernel()
{
    const int b  = blockIdx.z;
    const int p0 = blockIdx.y * 64, r0 = blockIdx.x * 64;
    const int tid = threadIdx.x;
    const int tp = tid >> 4, tr = tid & 15;
    __shared__ float As[16][64];    // [k][p]
    __shared__ float Bs[16][64];    // [k][r]
    __shared__ float red[8];
    const float* a  = g_al + b * (UU*KK);
    const float* qv = g_qv + b * (KK*UU);

    float acc[4][4];
    #pragma unroll
    for (int i = 0; i < 4; i++)
        #pragma unroll
        for (int j = 0; j < 4; j++) acc[i][j] = 0.f;

    for (int k0 = 0; k0 < KK; k0 += 16) {
        {   // As: 64p x 16k, store transposed
            int row = tid >> 2, c4 = tid & 3;
            int p = p0 + row;
            float4 av = make_float4(0.f, 0.f, 0.f, 0.f);
            if (p < UU)
                av = *reinterpret_cast<const float4*>(a + p * KK + k0 + c4 * 4);
            As[c4*4+0][row] = av.x;  As[c4*4+1][row] = av.y;
            As[c4*4+2][row] = av.z;  As[c4*4+3][row] = av.w;
        }
        {   // Bs: 16k x 64r (coalesced, qv is k-major)
            int row = tid >> 4, c4 = tid & 15;
            int r = r0 + c4 * 4;
            float4 bv = make_float4(0.f, 0.f, 0.f, 0.f);
            if (r < UU)
                bv = *reinterpret_cast<const float4*>(qv + (k0 + row) * UU + r);
            *reinterpret_cast<float4*>(&Bs[row][c4 * 4]) = bv;
        }
        __syncthreads();
        #pragma unroll
        for (int kk = 0; kk < 16; kk++) {
            float4 av = *reinterpret_cast<const float4*>(&As[kk][tp * 4]);
            float4 bv = *reinterpret_cast<const float4*>(&Bs[kk][tr * 4]);
            float ar[4] = {av.x, av.y, av.z, av.w};
            float br[4] = {bv.x, bv.y, bv.z, bv.w};
            #pragma unroll
            for (int i = 0; i < 4; i++)
                #pragma unroll
                for (int j = 0; j < 4; j++) acc[i][j] += ar[i] * br[j];
        }
        __syncthreads();
    }
    float a2v[4], b2v[4];
    #pragma unroll
    for (int i = 0; i < 4; i++) {
        int p = p0 + tp * 4 + i;
        a2v[i] = (p < UU) ? g_a2[b * UU + p] : 0.f;
    }
    #pragma unroll
    for (int j = 0; j < 4; j++) {
        int r = r0 + tr * 4 + j;
        b2v[j] = (r < UU) ? g_b2[b * UU + r] : 0.f;
    }
    float tsum = 0.f;
    #pragma unroll
    for (int i = 0; i < 4; i++) {
        int p = p0 + tp * 4 + i;
        #pragma unroll
        for (int j = 0; j < 4; j++) {
            int r = r0 + tr * 4 + j;
            if (p < UU && r < UU)
                tsum += fmaxf(a2v[i] + b2v[j] - 2.f * acc[i][j], 0.f);
        }
    }
    #pragma unroll
    for (int off = 16; off; off >>= 1)
        tsum += __shfl_down_sync(0xffffffffu, tsum, off);
    if ((tid & 31) == 0) red[tid >> 5] = tsum;
    __syncthreads();
    if (tid == 0) {
        float s = 0.f;
        #pragma unroll
        for (int w = 0; w < 8; w++) s += red[w];
        g_part[b * 169 + blockIdx.y * 13 + blockIdx.x] = s;
    }
}

// ============================================================================
// 7) Final: out[b] = sum(partials) / (784*784)
// ============================================================================
__global__ void final_kernel(float* __restrict__ out)
{
    __shared__ float red[8];
    const int b = blockIdx.x, tid = threadIdx.x;
    float s = (tid < 169) ? g_part[b * 169 + tid] : 0.f;
    #pragma unroll
    for (int off = 16; off; off >>= 1)
        s += __shfl_down_sync(0xffffffffu, s, off);
    if ((tid & 31) == 0) red[tid >> 5] = s;
    __syncthreads();
    if (tid == 0) {
        float t = 0.f;
        #pragma unroll
        for (int w = 0; w < 8; w++) t += red[w];
        out[b] = t * (1.0f / 614656.0f);   // / (784*784)
    }
}

// ============================================================================
extern "C" void kernel_launch(void* const* d_in, const int* in_sizes, int n_in,
                              void* d_out, int out_size)
{
    const float* query   = (const float*)d_in[0];   // (8,512,28,28)
    const float* support = (const float*)d_in[1];   // (16,512,28,28)
    const float* Wk      = (const float*)d_in[2];   // (128,512)
    const float* Wv      = (const float*)d_in[3];   // (128,512)
    float* out = (float*)d_out;                     // (8,) fp32

    proj_kernel     <<<dim3(13, 1, 48),  256        >>>(query, support, Wk, Wv);
    transpose_kernel<<<dim3(25, 4, 32),  dim3(32, 8)>>>();
    attn_kernel     <<<dim3(784, 8),     224        >>>();
    align_kernel    <<<dim3(784, 8),     128        >>>();
    b2_kernel       <<<dim3(4, 8),       256        >>>();
    dist_kernel     <<<dim3(13, 13, 8),  256        >>>();
    final_kernel    <<<8,                256        >>>(out);
}

// round 15
// speedup vs baseline: 1.0030x; 1.0030x over previous
#include <cuda_runtime.h>

// Shapes (fixed by the problem)
#define BB 8      // batch
#define NN 16     // support classes
#define DD 512    // input channels
#define UU 784    // H*W = 28*28 (spatial, both u and v)
#define KK 128    // projected dim DK

// -------------------- scratch (device globals; no allocs allowed) ----------
__device__ float g_qk [BB*KK*UU];   // [b][k][u]  Wk @ query
__device__ float g_qv [BB*KK*UU];   // [b][k][u]  Wv @ query   (= "b" matrix, k-major)
__device__ float g_sk [NN*KK*UU];   // [n][k][v]  Wk @ support
__device__ float g_sv [NN*KK*UU];   // [n][k][v]  Wv @ support
__device__ float g_skt[UU*NN*KK];   // [v][n][k]  transposed support keys
__device__ float g_svt[UU*NN*KK];   // [v][n][k]  transposed support values
__device__ float g_A  [BB*NN*UU];   // [b][n][v]  sum_u softmax_n(scores)
__device__ float g_al [BB*UU*KK];   // [b][v][k]  query_aligned (a matrix)
__device__ float g_a2 [BB*UU];      // ||a||^2 per (b,v)
__device__ float g_b2 [BB*UU];      // ||b||^2 per (b,u)
__device__ float g_part[BB*169];    // per-tile partial sums of clamped d2

// ============================================================================
// 1) Projections: out[g][k][u] = sum_d W[k][d] * x[g][d][u]
//    48 jobs: (8 b × {Wk,Wv}) on query, (16 n × {Wk,Wv}) on support.
//    Tile: BM=128 (all k), BN=64 (u), BK=16 (d). 256 thr, TM=8, TN=4.
// ============================================================================
__global__ __launch_bounds__(256) void proj_kernel(
    const float* __restrict__ query, const float* __restrict__ support,
    const float* __restrict__ Wk,    const float* __restrict__ Wv)
{
    int job = blockIdx.z;
    const float* x; float* out; const float* W;
    if (job < 16) {
        int g = job >> 1;
        x   = query + g * (DD*UU);
        W   = (job & 1) ? Wv : Wk;
        out = ((job & 1) ? g_qv : g_qk) + g * (KK*UU);
    } else {
        int idx = job - 16, g = idx >> 1;
        x   = support + g * (DD*UU);
        W   = (idx & 1) ? Wv : Wk;
        out = ((idx & 1) ? g_sv : g_sk) + g * (KK*UU);
    }
    const int u0  = blockIdx.x * 64;
    const int tid = threadIdx.x;
    const int ty  = tid >> 4;      // 0..15 -> k rows ty*8..+7
    const int tx  = tid & 15;      // 0..15 -> u cols tx*4..+3

    __shared__ float Ws[16][128];  // [d][k]  (transposed for conflict-free reads)
    __shared__ float Xs[16][64];   // [d][u]

    float acc[8][4];
    #pragma unroll
    for (int i = 0; i < 8; i++)
        #pragma unroll
        for (int j = 0; j < 4; j++) acc[i][j] = 0.f;

    for (int d0 = 0; d0 < DD; d0 += 16) {
        // W tile: 128k x 16d -> Ws[d][k]
        #pragma unroll
        for (int t = 0; t < 2; t++) {
            int t4 = tid * 2 + t;            // 0..511
            int k  = t4 >> 2;                // 0..127
            int c4 = t4 & 3;                 // 0..3
            float4 w = *reinterpret_cast<const float4*>(W + k * DD + d0 + c4 * 4);
            Ws[c4*4+0][k] = w.x;  Ws[c4*4+1][k] = w.y;
            Ws[c4*4+2][k] = w.z;  Ws[c4*4+3][k] = w.w;
        }
        // X tile: 16d x 64u
        {
            int row = tid >> 4;              // d
            int c4  = tid & 15;              // u/4
            int u   = u0 + c4 * 4;
            float4 xv = make_float4(0.f, 0.f, 0.f, 0.f);
            if (u < UU)
                xv = *reinterpret_cast<const float4*>(x + (d0 + row) * UU + u);
            *reinterpret_cast<float4*>(&Xs[row][c4 * 4]) = xv;
        }
        __syncthreads();
        #pragma unroll
        for (int dd = 0; dd < 16; dd++) {
            float4 wa = *reinterpret_cast<const float4*>(&Ws[dd][ty * 8]);
            float4 wb = *reinterpret_cast<const float4*>(&Ws[dd][ty * 8 + 4]);
            float4 xv = *reinterpret_cast<const float4*>(&Xs[dd][tx * 4]);
            float wr[8] = {wa.x, wa.y, wa.z, wa.w, wb.x, wb.y, wb.z, wb.w};
            float xr[4] = {xv.x, xv.y, xv.z, xv.w};
            #pragma unroll
            for (int i = 0; i < 8; i++)
                #pragma unroll
                for (int j = 0; j < 4; j++)
                    acc[i][j] += wr[i] * xr[j];
        }
        __syncthreads();
    }
    int u = u0 + tx * 4;
    if (u < UU) {
        #pragma unroll
        for (int i = 0; i < 8; i++) {
            int k = ty * 8 + i;
            float4 o = make_float4(acc[i][0], acc[i][1], acc[i][2], acc[i][3]);
            *reinterpret_cast<float4*>(out + k * UU + u) = o;
        }
    }
}

// ============================================================================
// 2) Transpose g_sk/g_sv [n][k][v] -> [v][n][k] for coalesced per-v access.
//    grid (25, 4, 32): x = v tile, y = k tile, z = n*2 + which
// ============================================================================
__global__ void transpose_kernel()
{
    const int which = blockIdx.z & 1;
    const int n     = blockIdx.z >> 1;
    const float* in = (which ? g_sv : g_sk) + n * (KK*UU);
    float* out      = (which ? g_svt : g_skt);
    __shared__ float s[32][33];
    const int v0 = blockIdx.x * 32, k0 = blockIdx.y * 32;
    const int tx = threadIdx.x, ty = threadIdx.y;   // 32 x 8
    #pragma unroll
    for (int j = 0; j < 4; j++) {
        int k = k0 + ty + j * 8, v = v0 + tx;
        s[ty + j * 8][tx] = (v < UU) ? in[k * UU + v] : 0.f;
    }
    __syncthreads();
    #pragma unroll
    for (int j = 0; j < 4; j++) {
        int v = v0 + ty + j * 8, k = k0 + tx;
        if (v < UU) out[v * (NN*KK) + n * KK + k] = s[tx][ty + j * 8];
    }
}

// ============================================================================
// 3) Attention: block = (v, b). Computes A[b][n][v] = sum_u softmax_n(scores).
//    Thread t<196 owns 4 consecutive u; keeps all 16 n in registers so the
//    softmax over n is thread-local (no cross-thread traffic). FFMA-bound.
// ============================================================================
__global__ __launch_bounds__(224, 2) void attn_kernel()
{
    const int v = blockIdx.x, b = blockIdx.y;
    const int tid = threadIdx.x;
    __shared__ float s_sk[NN * KK];     // [n][k] for this v
    __shared__ float s_red[7][16];

    for (int i = tid; i < NN * KK; i += 224)
        s_sk[i] = g_skt[v * (NN*KK) + i];
    __syncthreads();

    float partA[16];
    #pragma unroll
    for (int n = 0; n < 16; n++) partA[n] = 0.f;

    if (tid < 196) {
        const int u0 = tid * 4;         // 196*4 = 784 exactly
        float acc[64];                  // [n][uu]
        #pragma unroll
        for (int i = 0; i < 64; i++) acc[i] = 0.f;
        const float* qb = g_qk + b * (KK*UU) + u0;
        #pragma unroll 4
        for (int k = 0; k < KK; k++) {
            float4 q4 = *reinterpret_cast<const float4*>(qb + k * UU);
            #pragma unroll
            for (int n = 0; n < 16; n++) {
                float s = s_sk[n * KK + k];   // uniform -> broadcast LDS
                acc[n*4+0] += s * q4.x;
                acc[n*4+1] += s * q4.y;
                acc[n*4+2] += s * q4.z;
                acc[n*4+3] += s * q4.w;
            }
        }
        const float scale = 0.0883883476483184f;   // 1/sqrt(128)
        #pragma unroll
        for (int uu = 0; uu < 4; uu++) {
            float m = acc[uu];
            #pragma unroll
            for (int n = 1; n < 16; n++) m = fmaxf(m, acc[n*4+uu]);
            float e[16], sum = 0.f;
            #pragma unroll
            for (int n = 0; n < 16; n++) {
                e[n] = __expf((acc[n*4+uu] - m) * scale);
                sum += e[n];
            }
            float inv = 1.f / sum;
            #pragma unroll
            for (int n = 0; n < 16; n++) partA[n] += e[n] * inv;
        }
    }
    const int lane = tid & 31, warp = tid >> 5;
    #pragma unroll
    for (int n = 0; n < 16; n++) {
        float t = partA[n];
        #pragma unroll
        for (int off = 16; off; off >>= 1)
            t += __shfl_down_sync(0xffffffffu, t, off);
        if (lane == 0) s_red[warp][n] = t;
    }
    __syncthreads();
    if (tid < 16) {
        float s = 0.f;
        #pragma unroll
        for (int w = 0; w < 7; w++) s += s_red[w][tid];
        g_A[(b * 16 + tid) * UU + v] = s;
    }
}

// ============================================================================
// 4) Align: a[b][v][k] = sum_n A[b][n][v] * sv[n][k][v]; also a2[b][v].
// ============================================================================
__global__ __launch_bounds__(128) void align_kernel()
{
    const int v = blockIdx.x, b = blockIdx.y, k = threadIdx.x;
    __shared__ float a_sm[16];
    __shared__ float red[4];
    if (k < 16) a_sm[k] = g_A[(b * 16 + k) * UU + v];
    __syncthreads();
    const float* sv = g_svt + v * (NN*KK) + k;
    float acc = 0.f;
    #pragma unroll
    for (int n = 0; n < 16; n++) acc += a_sm[n] * sv[n * KK];
    g_al[(b * UU + v) * KK + k] = acc;
    float sq = acc * acc;
    #pragma unroll
    for (int off = 16; off; off >>= 1)
        sq += __shfl_down_sync(0xffffffffu, sq, off);
    if ((k & 31) == 0) red[k >> 5] = sq;
    __syncthreads();
    if (k == 0) g_a2[b * UU + v] = red[0] + red[1] + red[2] + red[3];
}

// ============================================================================
// 5) b2[b][u] = sum_k qv[b][k][u]^2
// ============================================================================
__global__ void b2_kernel()
{
    const int b = blockIdx.y;
    const int u = blockIdx.x * 256 + threadIdx.x;
    if (u >= UU) return;
    const float* q = g_qv + b * (KK*UU) + u;
    float s = 0.f;
    #pragma unroll 8
    for (int k = 0; k < KK; k++) { float x = q[k * UU]; s += x * x; }
    g_b2[b * UU + u] = s;
}

// ============================================================================
// 6) Distance: per b, sum_{p,r} max(a2[p]+b2[r]-2*dot(a[p,:],bmat[r,:]), 0).
//    a is [v][k] row-major, qv is already [k][u] -> classic C = A*B tiling.
//    64x64 tile, 256 thr, 4x4 per thread; tile partial -> g_part (deterministic).
// ============================================================================
__global__ __launch_bounds__(256) void dist_kernel()
{
    const int b  = blockIdx.z;
    const int p0 = blockIdx.y * 64, r0 = blockIdx.x * 64;
    const int tid = threadIdx.x;
    const int tp = tid >> 4, tr = tid & 15;
    __shared__ float As[16][64];    // [k][p]
    __shared__ float Bs[16][64];    // [k][r]
    __shared__ float red[8];
    const float* a  = g_al + b * (UU*KK);
    const float* qv = g_qv + b * (KK*UU);

    float acc[4][4];
    #pragma unroll
    for (int i = 0; i < 4; i++)
        #pragma unroll
        for (int j = 0; j < 4; j++) acc[i][j] = 0.f;

    for (int k0 = 0; k0 < KK; k0 += 16) {
        {   // As: 64p x 16k, store transposed
            int row = tid >> 2, c4 = tid & 3;
            int p = p0 + row;
            float4 av = make_float4(0.f, 0.f, 0.f, 0.f);
            if (p < UU)
                av = *reinterpret_cast<const float4*>(a + p * KK + k0 + c4 * 4);
            As[c4*4+0][row] = av.x;  As[c4*4+1][row] = av.y;
            As[c4*4+2][row] = av.z;  As[c4*4+3][row] = av.w;
        }
        {   // Bs: 16k x 64r (coalesced, qv is k-major)
            int row = tid >> 4, c4 = tid & 15;
            int r = r0 + c4 * 4;
            float4 bv = make_float4(0.f, 0.f, 0.f, 0.f);
            if (r < UU)
                bv = *reinterpret_cast<const float4*>(qv + (k0 + row) * UU + r);
            *reinterpret_cast<float4*>(&Bs[row][c4 * 4]) = bv;
        }
        __syncthreads();
        #pragma unroll
        for (int kk = 0; kk < 16; kk++) {
            float4 av = *reinterpret_cast<const float4*>(&As[kk][tp * 4]);
            float4 bv = *reinterpret_cast<const float4*>(&Bs[kk][tr * 4]);
            float ar[4] = {av.x, av.y, av.z, av.w};
            float br[4] = {bv.x, bv.y, bv.z, bv.w};
            #pragma unroll
            for (int i = 0; i < 4; i++)
                #pragma unroll
                for (int j = 0; j < 4; j++) acc[i][j] += ar[i] * br[j];
        }
        __syncthreads();
    }
    float a2v[4], b2v[4];
    #pragma unroll
    for (int i = 0; i < 4; i++) {
        int p = p0 + tp * 4 + i;
        a2v[i] = (p < UU) ? g_a2[b * UU + p] : 0.f;
    }
    #pragma unroll
    for (int j = 0; j < 4; j++) {
        int r = r0 + tr * 4 + j;
        b2v[j] = (r < UU) ? g_b2[b * UU + r] : 0.f;
    }
    float tsum = 0.f;
    #pragma unroll
    for (int i = 0; i < 4; i++) {
        int p = p0 + tp * 4 + i;
        #pragma unroll
        for (int j = 0; j < 4; j++) {
            int r = r0 + tr * 4 + j;
            if (p < UU && r < UU)
                tsum += fmaxf(a2v[i] + b2v[j] - 2.f * acc[i][j], 0.f);
        }
    }
    #pragma unroll
    for (int off = 16; off; off >>= 1)
        tsum += __shfl_down_sync(0xffffffffu, tsum, off);
    if ((tid & 31) == 0) red[tid >> 5] = tsum;
    __syncthreads();
    if (tid == 0) {
        float s = 0.f;
        #pragma unroll
        for (int w = 0; w < 8; w++) s += red[w];
        g_part[b * 169 + blockIdx.y * 13 + blockIdx.x] = s;
    }
}

// ============================================================================
// 7) Final: out[b] = sum(partials) / (784*784)
// ============================================================================
__global__ void final_kernel(float* __restrict__ out)
{
    __shared__ float red[8];
    const int b = blockIdx.x, tid = threadIdx.x;
    float s = (tid < 169) ? g_part[b * 169 + tid] : 0.f;
    #pragma unroll
    for (int off = 16; off; off >>= 1)
        s += __shfl_down_sync(0xffffffffu, s, off);
    if ((tid & 31) == 0) red[tid >> 5] = s;
    __syncthreads();
    if (tid == 0) {
        float t = 0.f;
        #pragma unroll
        for (int w = 0; w < 8; w++) t += red[w];
        out[b] = t * (1.0f / 614656.0f);   // / (784*784)
    }
}

// ============================================================================
extern "C" void kernel_launch(void* const* d_in, const int* in_sizes, int n_in,
                              void* d_out, int out_size)
{
    const float* query   = (const float*)d_in[0];   // (8,512,28,28)
    const float* support = (const float*)d_in[1];   // (16,512,28,28)
    const float* Wk      = (const float*)d_in[2];   // (128,512)
    const float* Wv      = (const float*)d_in[3];   // (128,512)
    float* out = (float*)d_out;                     // (8,) fp32

    proj_kernel     <<<dim3(13, 1, 48),  256        >>>(query, support, Wk, Wv);
    transpose_kernel<<<dim3(25, 4, 32),  dim3(32, 8)>>>();
    attn_kernel     <<<dim3(784, 8),     224        >>>();
    align_kernel    <<<dim3(784, 8),     128        >>>();
    b2_kernel       <<<dim3(4, 8),       256        >>>();
    dist_kernel     <<<dim3(13, 13, 8),  256        >>>();
    final_kernel    <<<8,                256        >>>(out);
}